// round 3
// baseline (speedup 1.0000x reference)
#include <cuda_runtime.h>

#define CCH 256
#define CMID 16
#define HWSZ 16384
#define NGRP 32

// ---- device scratch (no allocations) ----
__device__ float g_dw[201326592];   // [(proj*2+input)][b][c][hw] proj:0=q,1=k,2=v
__device__ float g_q[4194304];      // [input][b][m][hw]
__device__ float g_k[4194304];
__device__ float g_fused[33554432]; // [b][c][hw]
__device__ float g_psum[131072];    // [b][g][blk][2]
__device__ float2 g_stats[256];     // [b][g]

// ---- K1: fused depthwise 3x3 (q,k,v) on both inputs ----
__global__ __launch_bounds__(256) void dw_kernel(
    const float* __restrict__ img, const float* __restrict__ mask,
    const float* __restrict__ qw, const float* __restrict__ qb,
    const float* __restrict__ kw, const float* __restrict__ kb,
    const float* __restrict__ vw, const float* __restrict__ vb)
{
    int bid = blockIdx.x;
    int band = bid & 15;
    int bc = (bid >> 4) & 2047;
    int input = bid >> 15;
    int c = bc & 255;
    const float* src = (input ? mask : img) + (size_t)bc * HWSZ;

    __shared__ float s[10 * 132];
    int t = threadIdx.x;
    int y0 = band * 8;
    for (int i = t; i < 10 * 130; i += 256) {
        int r = i / 130, cc = i - r * 130;
        int gy = y0 - 1 + r, gx = cc - 1;
        float v = 0.f;
        if ((unsigned)gy < 128u && (unsigned)gx < 128u) v = src[gy * 128 + gx];
        s[r * 132 + cc] = v;
    }
    float wq[9], wk[9], wv[9];
#pragma unroll
    for (int j = 0; j < 9; j++) { wq[j]=qw[c*9+j]; wk[j]=kw[c*9+j]; wv[j]=vw[c*9+j]; }
    float bq = qb[c], bk = kb[c], bv = vb[c];
    __syncthreads();

    int x = t & 127, quad = t >> 7;
    float aq[4], ak[4], av[4];
#pragma unroll
    for (int r = 0; r < 4; r++) { aq[r]=bq; ak[r]=bk; av[r]=bv; }
#pragma unroll
    for (int dx = 0; dx < 3; dx++) {
        float col[6];
#pragma unroll
        for (int rr = 0; rr < 6; rr++) col[rr] = s[(quad*4+rr)*132 + x + dx];
#pragma unroll
        for (int r = 0; r < 4; r++)
#pragma unroll
            for (int dy = 0; dy < 3; dy++) {
                float v = col[r + dy]; int j = dy*3 + dx;
                aq[r] += wq[j]*v; ak[r] += wk[j]*v; av[r] += wv[j]*v;
            }
    }
    float* dq = g_dw + ((size_t)(0 + input)*2048 + bc)*(size_t)HWSZ;
    float* dk = g_dw + ((size_t)(2 + input)*2048 + bc)*(size_t)HWSZ;
    float* dv = g_dw + ((size_t)(4 + input)*2048 + bc)*(size_t)HWSZ;
#pragma unroll
    for (int r = 0; r < 4; r++) {
        int y = y0 + quad*4 + r;
        dq[y*128 + x] = aq[r]; dk[y*128 + x] = ak[r]; dv[y*128 + x] = av[r];
    }
}

// ---- K2: q/k pointwise (16x256 per pixel) ----
__global__ __launch_bounds__(256) void pwqk_kernel(
    const float* __restrict__ qpw_w, const float* __restrict__ qpw_b,
    const float* __restrict__ kpw_w, const float* __restrict__ kpw_b)
{
    int which = blockIdx.y;          // 0:q-img 1:q-mask 2:k-img 3:k-mask
    int input = which & 1, proj = which >> 1;
    const float* Wp = proj ? kpw_w : qpw_w;
    const float* bp = proj ? kpw_b : qpw_b;
    const float* dwb = g_dw + (size_t)(proj*2 + input)*2048*(size_t)HWSZ;
    float* outb = (proj ? g_k : g_q) + (size_t)input*8*CMID*HWSZ;

    __shared__ float4 ws[CMID*64];
    __shared__ float  bs[CMID];
    int t = threadIdx.x;
    for (int i = t; i < CMID*64; i += 256) ws[i] = ((const float4*)Wp)[i];
    if (t < CMID) bs[t] = bp[t];
    __syncthreads();

    int n = blockIdx.x*256 + t;
    int b = n >> 14, hw = n & 16383;
    const float* xp = dwb + ((size_t)b*CCH)*HWSZ + hw;
    float acc[CMID];
#pragma unroll
    for (int m = 0; m < CMID; m++) acc[m] = bs[m];
#pragma unroll 4
    for (int c4 = 0; c4 < 64; c4++) {
        float x0 = xp[(size_t)(4*c4+0)*HWSZ];
        float x1 = xp[(size_t)(4*c4+1)*HWSZ];
        float x2 = xp[(size_t)(4*c4+2)*HWSZ];
        float x3 = xp[(size_t)(4*c4+3)*HWSZ];
#pragma unroll
        for (int m = 0; m < CMID; m++) {
            float4 w = ws[m*64 + c4];
            acc[m] += w.x*x0 + w.y*x1 + w.z*x2 + w.w*x3;
        }
    }
    float* op = outb + ((size_t)b*CMID)*HWSZ + hw;
#pragma unroll
    for (int m = 0; m < CMID; m++) op[(size_t)m*HWSZ] = acc[m];
}

// ---- K3 helpers ----
__device__ __forceinline__ void qk_gemm(const float* sQ, const float* sK, float* sSt, int t)
{
    int tx = t & 15, ty = t >> 4;
    int q0 = tx*4, p0 = ty*4;
    float a[4][4];
#pragma unroll
    for (int i=0;i<4;i++)
#pragma unroll
        for (int j=0;j<4;j++) a[i][j]=0.f;
#pragma unroll
    for (int c = 0; c < 16; c++) {
        float4 kk = *(const float4*)&sK[c*64 + q0];
        float4 qq = *(const float4*)&sQ[c*64 + p0];
        float kr[4]={kk.x,kk.y,kk.z,kk.w}, qr[4]={qq.x,qq.y,qq.z,qq.w};
#pragma unroll
        for (int i=0;i<4;i++)
#pragma unroll
            for (int j=0;j<4;j++) a[i][j] += kr[i]*qr[j];
    }
#pragma unroll
    for (int i=0;i<4;i++)
#pragma unroll
        for (int j=0;j<4;j++) sSt[(q0+i)*68 + p0+j] = 0.25f*a[i][j];
}

__device__ __forceinline__ void softmax_col(float* sSt, int p, float scale)
{
    float mx = -1e30f;
    for (int q = 0; q < 64; q++) mx = fmaxf(mx, sSt[q*68+p]);
    float sum = 0.f;
    for (int q = 0; q < 64; q++) { float e = __expf(sSt[q*68+p]-mx); sSt[q*68+p]=e; sum+=e; }
    float inv = scale / sum;
    for (int q = 0; q < 64; q++) sSt[q*68+p] *= inv;
}

__device__ __forceinline__ void t_accum(float acc[8][8], const float* sV, const float* sSt,
                                        int c0, int p0)
{
#pragma unroll 2
    for (int q = 0; q < 64; q++) {
        float av[8];
#pragma unroll
        for (int i=0;i<8;i++) av[i] = sV[(c0+i)*65 + q];
        float4 u0 = *(const float4*)&sSt[q*68 + p0];
        float4 u1 = *(const float4*)&sSt[q*68 + p0 + 4];
        float uu[8]={u0.x,u0.y,u0.z,u0.w,u1.x,u1.y,u1.z,u1.w};
#pragma unroll
        for (int i=0;i<8;i++)
#pragma unroll
            for (int j=0;j<8;j++) acc[i][j] += av[i]*uu[j];
    }
}

// smem layout (floats): Q 0..1024, K 1024..2048, St1 2048(4352), St2 6400(4352),
// V/U union 10752(17408), W 28160(4160)  -> 32320 floats = 129280 B
#define SMEM_FLOATS 32320

// ---- K3: attention both directions + Wv GEMM + residual + GN partials ----
__global__ __launch_bounds__(256, 1) void attn_kernel(
    const float* __restrict__ img, const float* __restrict__ mask,
    const float* __restrict__ vpw_w, const float* __restrict__ vpw_b,
    const float* __restrict__ alpha_p, const float* __restrict__ beta_p)
{
    extern __shared__ float sm[];
    float* sQ   = sm;
    float* sK   = sm + 1024;
    float* sSt1 = sm + 2048;
    float* sSt2 = sm + 6400;
    float* sV   = sm + 10752;   // stride 65, also reused as sU (stride 68)
    float* sU   = sm + 10752;
    float* sW   = sm + 28160;   // 16 x 260

    int t = threadIdx.x;
    int bid = blockIdx.x;
    int b = bid >> 8, blkid = bid & 255;
    int by = blkid >> 4, bx = blkid & 15;
    float al = __ldg(alpha_p), be = __ldg(beta_p);
    int hw00 = by*8*128 + bx*8;

    // dir1: Q=mask, K=img
    {
        const float* qs = g_q + (((size_t)8 + b)*CMID)*HWSZ;
        const float* ks = g_k + (((size_t)0 + b)*CMID)*HWSZ;
        for (int e = t; e < 1024; e += 256) {
            int m = e >> 6, p = e & 63;
            int hw = hw00 + ((p>>3)<<7) + (p&7);
            sQ[m*64+p] = qs[(size_t)m*HWSZ + hw];
            sK[m*64+p] = ks[(size_t)m*HWSZ + hw];
        }
    }
    __syncthreads();
    qk_gemm(sQ, sK, sSt1, t);
    __syncthreads();
    // dir2 load + softmax(St1, alpha)
    {
        const float* qs = g_q + (((size_t)0 + b)*CMID)*HWSZ;
        const float* ks = g_k + (((size_t)8 + b)*CMID)*HWSZ;
        for (int e = t; e < 1024; e += 256) {
            int m = e >> 6, p = e & 63;
            int hw = hw00 + ((p>>3)<<7) + (p&7);
            sQ[m*64+p] = qs[(size_t)m*HWSZ + hw];
            sK[m*64+p] = ks[(size_t)m*HWSZ + hw];
        }
        if (t < 64) softmax_col(sSt1, t, al);
    }
    __syncthreads();
    qk_gemm(sQ, sK, sSt2, t);
    __syncthreads();
    // load dwv(img) + softmax(St2, beta)
    {
        const float* vs = g_dw + (((size_t)4*8 + b)*CCH)*(size_t)HWSZ;
        for (int e = t; e < 256*64; e += 256) {
            int c = e >> 6, q = e & 63;
            int hw = hw00 + ((q>>3)<<7) + (q&7);
            sV[c*65+q] = vs[(size_t)c*HWSZ + hw];
        }
        if (t < 64) softmax_col(sSt2, t, be);
    }
    __syncthreads();

    int pg = t & 7, cg = t >> 3;
    int c0 = cg*8, p0 = pg*8;
    float acc[8][8];
#pragma unroll
    for (int i=0;i<8;i++)
#pragma unroll
        for (int j=0;j<8;j++) acc[i][j]=0.f;

    t_accum(acc, sV, sSt1, c0, p0);     // alpha folded in St1
    __syncthreads();
    {
        const float* vs = g_dw + (((size_t)5*8 + b)*CCH)*(size_t)HWSZ;
        for (int e = t; e < 256*64; e += 256) {
            int c = e >> 6, q = e & 63;
            int hw = hw00 + ((q>>3)<<7) + (q&7);
            sV[c*65+q] = vs[(size_t)c*HWSZ + hw];
        }
    }
    __syncthreads();
    t_accum(acc, sV, sSt2, c0, p0);     // beta folded in St2
    __syncthreads();
    // spill U (overwrites sV region)
#pragma unroll
    for (int i = 0; i < 8; i++) {
        *(float4*)&sU[(c0+i)*68 + p0]     = make_float4(acc[i][0],acc[i][1],acc[i][2],acc[i][3]);
        *(float4*)&sU[(c0+i)*68 + p0 + 4] = make_float4(acc[i][4],acc[i][5],acc[i][6],acc[i][7]);
    }
    __syncthreads();

    // fused = Wv * U + (al+be)*bv
    float ab = al + be;
#pragma unroll
    for (int i = 0; i < 8; i++) {
        float bv = vpw_b[c0+i];
#pragma unroll
        for (int j = 0; j < 8; j++) acc[i][j] = ab*bv;
    }
    for (int kc = 0; kc < 256; kc += 16) {
        for (int e = t; e < 4096; e += 256) {
            int o = e >> 4, cx = e & 15;
            sW[cx*260 + o] = vpw_w[o*256 + kc + cx];
        }
        __syncthreads();
#pragma unroll
        for (int cx = 0; cx < 16; cx++) {
            float4 w0 = *(const float4*)&sW[cx*260 + c0];
            float4 w1 = *(const float4*)&sW[cx*260 + c0 + 4];
            float4 u0 = *(const float4*)&sU[(kc+cx)*68 + p0];
            float4 u1 = *(const float4*)&sU[(kc+cx)*68 + p0 + 4];
            float wr[8]={w0.x,w0.y,w0.z,w0.w,w1.x,w1.y,w1.z,w1.w};
            float ur[8]={u0.x,u0.y,u0.z,u0.w,u1.x,u1.y,u1.z,u1.w};
#pragma unroll
            for (int i=0;i<8;i++)
#pragma unroll
                for (int j=0;j<8;j++) acc[i][j] += wr[i]*ur[j];
        }
        __syncthreads();
    }

    // epilogue: + img + mask, write fused, GN partial sums (deterministic)
    float lsum = 0.f, lsq = 0.f;
    size_t gb0 = (((size_t)b*CCH + c0) << 14) + (size_t)hw00 + ((size_t)pg << 7);
#pragma unroll
    for (int i = 0; i < 8; i++) {
        size_t ga = gb0 + ((size_t)i << 14);
        float4 i0 = *(const float4*)&img[ga];
        float4 i1 = *(const float4*)&img[ga+4];
        float4 m0 = *(const float4*)&mask[ga];
        float4 m1 = *(const float4*)&mask[ga+4];
        float4 r0, r1;
        r0.x=acc[i][0]+i0.x+m0.x; r0.y=acc[i][1]+i0.y+m0.y;
        r0.z=acc[i][2]+i0.z+m0.z; r0.w=acc[i][3]+i0.w+m0.w;
        r1.x=acc[i][4]+i1.x+m1.x; r1.y=acc[i][5]+i1.y+m1.y;
        r1.z=acc[i][6]+i1.z+m1.z; r1.w=acc[i][7]+i1.w+m1.w;
        *(float4*)&g_fused[ga]   = r0;
        *(float4*)&g_fused[ga+4] = r1;
        lsum += r0.x+r0.y+r0.z+r0.w + r1.x+r1.y+r1.z+r1.w;
        lsq  += r0.x*r0.x+r0.y*r0.y+r0.z*r0.z+r0.w*r0.w
              + r1.x*r1.x+r1.y*r1.y+r1.z*r1.z+r1.w*r1.w;
    }
#pragma unroll
    for (int off = 1; off < 8; off <<= 1) {
        lsum += __shfl_xor_sync(0xffffffffu, lsum, off);
        lsq  += __shfl_xor_sync(0xffffffffu, lsq, off);
    }
    if (pg == 0) {
        int idx = ((b*NGRP + cg)*256 + blkid)*2;
        g_psum[idx] = lsum; g_psum[idx+1] = lsq;
    }
}

// ---- K4: reduce GN partials ----
__global__ __launch_bounds__(256) void stats_kernel()
{
    int bg = blockIdx.x, t = threadIdx.x;
    float2 v = ((const float2*)g_psum)[bg*256 + t];
    float s = v.x, q = v.y;
#pragma unroll
    for (int o = 16; o; o >>= 1) {
        s += __shfl_xor_sync(0xffffffffu, s, o);
        q += __shfl_xor_sync(0xffffffffu, q, o);
    }
    __shared__ float ss[8], qs[8];
    if ((t & 31) == 0) { ss[t>>5] = s; qs[t>>5] = q; }
    __syncthreads();
    if (t == 0) {
        for (int w = 1; w < 8; w++) { s += ss[w]; q += qs[w]; }
        float inv = 1.f / 131072.f;
        float mu = s * inv;
        float var = q * inv - mu*mu;
        g_stats[bg] = make_float2(mu, rsqrtf(var + 1e-5f));
    }
}

// ---- K5: normalize ----
__global__ __launch_bounds__(1024) void norm_kernel(
    float* __restrict__ out, const float* __restrict__ gamma, const float* __restrict__ beta)
{
    int i4 = blockIdx.x*1024 + threadIdx.x;
    size_t e = (size_t)i4 << 2;
    int b = (int)(e >> 22), c = (int)(e >> 14) & 255;
    float2 st = g_stats[b*32 + (c >> 3)];
    float gsc = gamma[c] * st.y;
    float bsh = beta[c] - st.x * gsc;
    float4 f = *(const float4*)&g_fused[e];
    float4 r;
    r.x = f.x*gsc + bsh; r.y = f.y*gsc + bsh;
    r.z = f.z*gsc + bsh; r.w = f.w*gsc + bsh;
    *(float4*)&out[e] = r;
}

extern "C" void kernel_launch(void* const* d_in, const int* in_sizes, int n_in,
                              void* d_out, int out_size)
{
    const float* img    = (const float*)d_in[0];
    const float* mask   = (const float*)d_in[1];
    const float* qdw_w  = (const float*)d_in[2];
    const float* qdw_b  = (const float*)d_in[3];
    const float* kdw_w  = (const float*)d_in[4];
    const float* kdw_b  = (const float*)d_in[5];
    const float* vdw_w  = (const float*)d_in[6];
    const float* vdw_b  = (const float*)d_in[7];
    const float* qpw_w  = (const float*)d_in[8];
    const float* qpw_b  = (const float*)d_in[9];
    const float* kpw_w  = (const float*)d_in[10];
    const float* kpw_b  = (const float*)d_in[11];
    const float* vpw_w  = (const float*)d_in[12];
    const float* vpw_b  = (const float*)d_in[13];
    const float* alpha  = (const float*)d_in[14];
    const float* beta   = (const float*)d_in[15];
    const float* gn_w   = (const float*)d_in[16];
    const float* gn_b   = (const float*)d_in[17];

    cudaFuncSetAttribute(attn_kernel, cudaFuncAttributeMaxDynamicSharedMemorySize,
                         SMEM_FLOATS * 4);

    dw_kernel<<<65536, 256>>>(img, mask, qdw_w, qdw_b, kdw_w, kdw_b, vdw_w, vdw_b);
    dim3 g2(512, 4);
    pwqk_kernel<<<g2, 256>>>(qpw_w, qpw_b, kpw_w, kpw_b);
    attn_kernel<<<2048, 256, SMEM_FLOATS * 4>>>(img, mask, vpw_w, vpw_b, alpha, beta);
    stats_kernel<<<256, 256>>>();
    norm_kernel<<<8192, 1024>>>((float*)d_out, gn_w, gn_b);
}

// round 4
// speedup vs baseline: 1.0116x; 1.0116x over previous
#include <cuda_runtime.h>

#define CCH 256
#define CMID 16
#define HWSZ 16384
#define NGRP 32

// ---- device scratch (no allocations) ----
__device__ float g_dw[201326592];   // [(proj*2+input)][b][c][hw] proj:0=q,1=k,2=v
__device__ float g_q[4194304];      // [input][b][m][hw]
__device__ float g_k[4194304];
__device__ float g_fused[33554432]; // [b][c][hw]
__device__ float g_psum[131072];    // [b][g][blk][2]
__device__ float2 g_stats[256];     // [b][g]

// ---- K1: fused depthwise 3x3 (q,k,v) on both inputs ----
__global__ __launch_bounds__(256) void dw_kernel(
    const float* __restrict__ img, const float* __restrict__ mask,
    const float* __restrict__ qw, const float* __restrict__ qb,
    const float* __restrict__ kw, const float* __restrict__ kb,
    const float* __restrict__ vw, const float* __restrict__ vb)
{
    int bid = blockIdx.x;
    int band = bid & 15;
    int bc = (bid >> 4) & 2047;
    int input = bid >> 15;
    int c = bc & 255;
    const float* src = (input ? mask : img) + (size_t)bc * HWSZ;

    __shared__ float s[10 * 132];
    int t = threadIdx.x;
    int y0 = band * 8;
    for (int i = t; i < 10 * 130; i += 256) {
        int r = i / 130, cc = i - r * 130;
        int gy = y0 - 1 + r, gx = cc - 1;
        float v = 0.f;
        if ((unsigned)gy < 128u && (unsigned)gx < 128u) v = src[gy * 128 + gx];
        s[r * 132 + cc] = v;
    }
    float wq[9], wk[9], wv[9];
#pragma unroll
    for (int j = 0; j < 9; j++) { wq[j]=qw[c*9+j]; wk[j]=kw[c*9+j]; wv[j]=vw[c*9+j]; }
    float bq = qb[c], bk = kb[c], bv = vb[c];
    __syncthreads();

    int x = t & 127, quad = t >> 7;
    float aq[4], ak[4], av[4];
#pragma unroll
    for (int r = 0; r < 4; r++) { aq[r]=bq; ak[r]=bk; av[r]=bv; }
#pragma unroll
    for (int dx = 0; dx < 3; dx++) {
        float col[6];
#pragma unroll
        for (int rr = 0; rr < 6; rr++) col[rr] = s[(quad*4+rr)*132 + x + dx];
#pragma unroll
        for (int r = 0; r < 4; r++)
#pragma unroll
            for (int dy = 0; dy < 3; dy++) {
                float v = col[r + dy]; int j = dy*3 + dx;
                aq[r] += wq[j]*v; ak[r] += wk[j]*v; av[r] += wv[j]*v;
            }
    }
    float* dq = g_dw + ((size_t)(0 + input)*2048 + bc)*(size_t)HWSZ;
    float* dk = g_dw + ((size_t)(2 + input)*2048 + bc)*(size_t)HWSZ;
    float* dv = g_dw + ((size_t)(4 + input)*2048 + bc)*(size_t)HWSZ;
#pragma unroll
    for (int r = 0; r < 4; r++) {
        int y = y0 + quad*4 + r;
        dq[y*128 + x] = aq[r]; dk[y*128 + x] = ak[r]; dv[y*128 + x] = av[r];
    }
}

// ---- K2: q/k pointwise (16x256 per pixel) ----
__global__ __launch_bounds__(256) void pwqk_kernel(
    const float* __restrict__ qpw_w, const float* __restrict__ qpw_b,
    const float* __restrict__ kpw_w, const float* __restrict__ kpw_b)
{
    int which = blockIdx.y;          // 0:q-img 1:q-mask 2:k-img 3:k-mask
    int input = which & 1, proj = which >> 1;
    const float* Wp = proj ? kpw_w : qpw_w;
    const float* bp = proj ? kpw_b : qpw_b;
    const float* dwb = g_dw + (size_t)(proj*2 + input)*2048*(size_t)HWSZ;
    float* outb = (proj ? g_k : g_q) + (size_t)input*8*CMID*HWSZ;

    __shared__ float4 ws[CMID*64];
    __shared__ float  bs[CMID];
    int t = threadIdx.x;
    for (int i = t; i < CMID*64; i += 256) ws[i] = ((const float4*)Wp)[i];
    if (t < CMID) bs[t] = bp[t];
    __syncthreads();

    int n = blockIdx.x*256 + t;
    int b = n >> 14, hw = n & 16383;
    const float* xp = dwb + ((size_t)b*CCH)*HWSZ + hw;
    float acc[CMID];
#pragma unroll
    for (int m = 0; m < CMID; m++) acc[m] = bs[m];
#pragma unroll 4
    for (int c4 = 0; c4 < 64; c4++) {
        float x0 = xp[(size_t)(4*c4+0)*HWSZ];
        float x1 = xp[(size_t)(4*c4+1)*HWSZ];
        float x2 = xp[(size_t)(4*c4+2)*HWSZ];
        float x3 = xp[(size_t)(4*c4+3)*HWSZ];
#pragma unroll
        for (int m = 0; m < CMID; m++) {
            float4 w = ws[m*64 + c4];
            acc[m] += w.x*x0 + w.y*x1 + w.z*x2 + w.w*x3;
        }
    }
    float* op = outb + ((size_t)b*CMID)*HWSZ + hw;
#pragma unroll
    for (int m = 0; m < CMID; m++) op[(size_t)m*HWSZ] = acc[m];
}

// ---- K3 helpers ----
__device__ __forceinline__ void qk_gemm(const float* sQ, const float* sK, float* sSt, int t)
{
    int tx = t & 15, ty = t >> 4;
    int q0 = tx*4, p0 = ty*4;
    float a[4][4];
#pragma unroll
    for (int i=0;i<4;i++)
#pragma unroll
        for (int j=0;j<4;j++) a[i][j]=0.f;
#pragma unroll
    for (int c = 0; c < 16; c++) {
        float4 kk = *(const float4*)&sK[c*64 + q0];
        float4 qq = *(const float4*)&sQ[c*64 + p0];
        float kr[4]={kk.x,kk.y,kk.z,kk.w}, qr[4]={qq.x,qq.y,qq.z,qq.w};
#pragma unroll
        for (int i=0;i<4;i++)
#pragma unroll
            for (int j=0;j<4;j++) a[i][j] += kr[i]*qr[j];
    }
#pragma unroll
    for (int i=0;i<4;i++)
#pragma unroll
        for (int j=0;j<4;j++) sSt[(q0+i)*68 + p0+j] = 0.25f*a[i][j];
}

__device__ __forceinline__ void softmax_col(float* sSt, int p, float scale)
{
    float mx = -1e30f;
    for (int q = 0; q < 64; q++) mx = fmaxf(mx, sSt[q*68+p]);
    float sum = 0.f;
    for (int q = 0; q < 64; q++) { float e = __expf(sSt[q*68+p]-mx); sSt[q*68+p]=e; sum+=e; }
    float inv = scale / sum;
    for (int q = 0; q < 64; q++) sSt[q*68+p] *= inv;
}

__device__ __forceinline__ void t_accum(float acc[8][8], const float* sV, const float* sSt,
                                        int c0, int p0)
{
#pragma unroll 2
    for (int q = 0; q < 64; q++) {
        float av[8];
#pragma unroll
        for (int i=0;i<8;i++) av[i] = sV[(c0+i)*65 + q];
        float4 u0 = *(const float4*)&sSt[q*68 + p0];
        float4 u1 = *(const float4*)&sSt[q*68 + p0 + 4];
        float uu[8]={u0.x,u0.y,u0.z,u0.w,u1.x,u1.y,u1.z,u1.w};
#pragma unroll
        for (int i=0;i<8;i++)
#pragma unroll
            for (int j=0;j<8;j++) acc[i][j] += av[i]*uu[j];
    }
}

// smem layout (floats): Q 0..1024, K 1024..2048, St1 2048(4352), St2 6400(4352),
// V/U union 10752(17408), W 28160(4160)  -> 32320 floats = 129280 B
#define SMEM_FLOATS 32320

// ---- K3: attention both directions + Wv GEMM + residual + GN partials ----
__global__ __launch_bounds__(256, 1) void attn_kernel(
    const float* __restrict__ img, const float* __restrict__ mask,
    const float* __restrict__ vpw_w, const float* __restrict__ vpw_b,
    const float* __restrict__ alpha_p, const float* __restrict__ beta_p)
{
    extern __shared__ float sm[];
    float* sQ   = sm;
    float* sK   = sm + 1024;
    float* sSt1 = sm + 2048;
    float* sSt2 = sm + 6400;
    float* sV   = sm + 10752;   // stride 65, also reused as sU (stride 68)
    float* sU   = sm + 10752;
    float* sW   = sm + 28160;   // 16 x 260

    int t = threadIdx.x;
    int bid = blockIdx.x;
    int b = bid >> 8, blkid = bid & 255;
    int by = blkid >> 4, bx = blkid & 15;
    float al = __ldg(alpha_p), be = __ldg(beta_p);
    int hw00 = by*8*128 + bx*8;

    // dir1: Q=mask, K=img
    {
        const float* qs = g_q + (((size_t)8 + b)*CMID)*HWSZ;
        const float* ks = g_k + (((size_t)0 + b)*CMID)*HWSZ;
        for (int e = t; e < 1024; e += 256) {
            int m = e >> 6, p = e & 63;
            int hw = hw00 + ((p>>3)<<7) + (p&7);
            sQ[m*64+p] = qs[(size_t)m*HWSZ + hw];
            sK[m*64+p] = ks[(size_t)m*HWSZ + hw];
        }
    }
    __syncthreads();
    qk_gemm(sQ, sK, sSt1, t);
    __syncthreads();
    // dir2 load + softmax(St1, alpha)
    {
        const float* qs = g_q + (((size_t)0 + b)*CMID)*HWSZ;
        const float* ks = g_k + (((size_t)8 + b)*CMID)*HWSZ;
        for (int e = t; e < 1024; e += 256) {
            int m = e >> 6, p = e & 63;
            int hw = hw00 + ((p>>3)<<7) + (p&7);
            sQ[m*64+p] = qs[(size_t)m*HWSZ + hw];
            sK[m*64+p] = ks[(size_t)m*HWSZ + hw];
        }
        if (t < 64) softmax_col(sSt1, t, al);
    }
    __syncthreads();
    qk_gemm(sQ, sK, sSt2, t);
    __syncthreads();
    // load dwv(img) + softmax(St2, beta)
    {
        const float* vs = g_dw + (((size_t)4*8 + b)*CCH)*(size_t)HWSZ;
        for (int e = t; e < 256*64; e += 256) {
            int c = e >> 6, q = e & 63;
            int hw = hw00 + ((q>>3)<<7) + (q&7);
            sV[c*65+q] = vs[(size_t)c*HWSZ + hw];
        }
        if (t < 64) softmax_col(sSt2, t, be);
    }
    __syncthreads();

    int pg = t & 7, cg = t >> 3;
    int c0 = cg*8, p0 = pg*8;
    float acc[8][8];
#pragma unroll
    for (int i=0;i<8;i++)
#pragma unroll
        for (int j=0;j<8;j++) acc[i][j]=0.f;

    t_accum(acc, sV, sSt1, c0, p0);     // alpha folded in St1
    __syncthreads();
    {
        const float* vs = g_dw + (((size_t)5*8 + b)*CCH)*(size_t)HWSZ;
        for (int e = t; e < 256*64; e += 256) {
            int c = e >> 6, q = e & 63;
            int hw = hw00 + ((q>>3)<<7) + (q&7);
            sV[c*65+q] = vs[(size_t)c*HWSZ + hw];
        }
    }
    __syncthreads();
    t_accum(acc, sV, sSt2, c0, p0);     // beta folded in St2
    __syncthreads();
    // spill U (overwrites sV region)
#pragma unroll
    for (int i = 0; i < 8; i++) {
        *(float4*)&sU[(c0+i)*68 + p0]     = make_float4(acc[i][0],acc[i][1],acc[i][2],acc[i][3]);
        *(float4*)&sU[(c0+i)*68 + p0 + 4] = make_float4(acc[i][4],acc[i][5],acc[i][6],acc[i][7]);
    }
    __syncthreads();

    // fused = Wv * U + (al+be)*bv
    float ab = al + be;
#pragma unroll
    for (int i = 0; i < 8; i++) {
        float bv = vpw_b[c0+i];
#pragma unroll
        for (int j = 0; j < 8; j++) acc[i][j] = ab*bv;
    }
    for (int kc = 0; kc < 256; kc += 16) {
        for (int e = t; e < 4096; e += 256) {
            int o = e >> 4, cx = e & 15;
            sW[cx*260 + o] = vpw_w[o*256 + kc + cx];
        }
        __syncthreads();
#pragma unroll
        for (int cx = 0; cx < 16; cx++) {
            float4 w0 = *(const float4*)&sW[cx*260 + c0];
            float4 w1 = *(const float4*)&sW[cx*260 + c0 + 4];
            float4 u0 = *(const float4*)&sU[(kc+cx)*68 + p0];
            float4 u1 = *(const float4*)&sU[(kc+cx)*68 + p0 + 4];
            float wr[8]={w0.x,w0.y,w0.z,w0.w,w1.x,w1.y,w1.z,w1.w};
            float ur[8]={u0.x,u0.y,u0.z,u0.w,u1.x,u1.y,u1.z,u1.w};
#pragma unroll
            for (int i=0;i<8;i++)
#pragma unroll
                for (int j=0;j<8;j++) acc[i][j] += wr[i]*ur[j];
        }
        __syncthreads();
    }

    // epilogue: + img + mask, write fused, GN partial sums (deterministic)
    float lsum = 0.f, lsq = 0.f;
    size_t gb0 = (((size_t)b*CCH + c0) << 14) + (size_t)hw00 + ((size_t)pg << 7);
#pragma unroll
    for (int i = 0; i < 8; i++) {
        size_t ga = gb0 + ((size_t)i << 14);
        float4 i0 = *(const float4*)&img[ga];
        float4 i1 = *(const float4*)&img[ga+4];
        float4 m0 = *(const float4*)&mask[ga];
        float4 m1 = *(const float4*)&mask[ga+4];
        float4 r0, r1;
        r0.x=acc[i][0]+i0.x+m0.x; r0.y=acc[i][1]+i0.y+m0.y;
        r0.z=acc[i][2]+i0.z+m0.z; r0.w=acc[i][3]+i0.w+m0.w;
        r1.x=acc[i][4]+i1.x+m1.x; r1.y=acc[i][5]+i1.y+m1.y;
        r1.z=acc[i][6]+i1.z+m1.z; r1.w=acc[i][7]+i1.w+m1.w;
        *(float4*)&g_fused[ga]   = r0;
        *(float4*)&g_fused[ga+4] = r1;
        lsum += r0.x+r0.y+r0.z+r0.w + r1.x+r1.y+r1.z+r1.w;
        lsq  += r0.x*r0.x+r0.y*r0.y+r0.z*r0.z+r0.w*r0.w
              + r1.x*r1.x+r1.y*r1.y+r1.z*r1.z+r1.w*r1.w;
    }
#pragma unroll
    for (int off = 1; off < 8; off <<= 1) {
        lsum += __shfl_xor_sync(0xffffffffu, lsum, off);
        lsq  += __shfl_xor_sync(0xffffffffu, lsq, off);
    }
    if (pg == 0) {
        int idx = ((b*NGRP + cg)*256 + blkid)*2;
        g_psum[idx] = lsum; g_psum[idx+1] = lsq;
    }
}

// ---- K4: reduce GN partials ----
__global__ __launch_bounds__(256) void stats_kernel()
{
    int bg = blockIdx.x, t = threadIdx.x;
    float2 v = ((const float2*)g_psum)[bg*256 + t];
    float s = v.x, q = v.y;
#pragma unroll
    for (int o = 16; o; o >>= 1) {
        s += __shfl_xor_sync(0xffffffffu, s, o);
        q += __shfl_xor_sync(0xffffffffu, q, o);
    }
    __shared__ float ss[8], qs[8];
    if ((t & 31) == 0) { ss[t>>5] = s; qs[t>>5] = q; }
    __syncthreads();
    if (t == 0) {
        for (int w = 1; w < 8; w++) { s += ss[w]; q += qs[w]; }
        float inv = 1.f / 131072.f;
        float mu = s * inv;
        float var = q * inv - mu*mu;
        g_stats[bg] = make_float2(mu, rsqrtf(var + 1e-5f));
    }
}

// ---- K5: normalize ----
__global__ __launch_bounds__(1024) void norm_kernel(
    float* __restrict__ out, const float* __restrict__ gamma, const float* __restrict__ beta)
{
    int i4 = blockIdx.x*1024 + threadIdx.x;
    size_t e = (size_t)i4 << 2;
    int b = (int)(e >> 22), c = (int)(e >> 14) & 255;
    float2 st = g_stats[b*32 + (c >> 3)];
    float gsc = gamma[c] * st.y;
    float bsh = beta[c] - st.x * gsc;
    float4 f = *(const float4*)&g_fused[e];
    float4 r;
    r.x = f.x*gsc + bsh; r.y = f.y*gsc + bsh;
    r.z = f.z*gsc + bsh; r.w = f.w*gsc + bsh;
    *(float4*)&out[e] = r;
}

extern "C" void kernel_launch(void* const* d_in, const int* in_sizes, int n_in,
                              void* d_out, int out_size)
{
    const float* img    = (const float*)d_in[0];
    const float* mask   = (const float*)d_in[1];
    const float* qdw_w  = (const float*)d_in[2];
    const float* qdw_b  = (const float*)d_in[3];
    const float* kdw_w  = (const float*)d_in[4];
    const float* kdw_b  = (const float*)d_in[5];
    const float* vdw_w  = (const float*)d_in[6];
    const float* vdw_b  = (const float*)d_in[7];
    const float* qpw_w  = (const float*)d_in[8];
    const float* qpw_b  = (const float*)d_in[9];
    const float* kpw_w  = (const float*)d_in[10];
    const float* kpw_b  = (const float*)d_in[11];
    const float* vpw_w  = (const float*)d_in[12];
    const float* vpw_b  = (const float*)d_in[13];
    const float* alpha  = (const float*)d_in[14];
    const float* beta   = (const float*)d_in[15];
    const float* gn_w   = (const float*)d_in[16];
    const float* gn_b   = (const float*)d_in[17];

    cudaFuncSetAttribute(attn_kernel, cudaFuncAttributeMaxDynamicSharedMemorySize,
                         SMEM_FLOATS * 4);

    dw_kernel<<<65536, 256>>>(img, mask, qdw_w, qdw_b, kdw_w, kdw_b, vdw_w, vdw_b);
    dim3 g2(512, 4);
    pwqk_kernel<<<g2, 256>>>(qpw_w, qpw_b, kpw_w, kpw_b);
    attn_kernel<<<2048, 256, SMEM_FLOATS * 4>>>(img, mask, vpw_w, vpw_b, alpha, beta);
    stats_kernel<<<256, 256>>>();
    norm_kernel<<<8192, 1024>>>((float*)d_out, gn_w, gn_b);
}

// round 5
// speedup vs baseline: 1.4197x; 1.4034x over previous
#include <cuda_runtime.h>

#define CCH 256
#define CMID 16
#define HWSZ 16384
#define NGRP 32

// ---- device scratch (no allocations) ----
// g_dw: [(proj*2+input)][b][c][hw] proj:0=q,1=k,2=v. After K2 consumes q/k dw,
// region 0 (first 33554432 floats) is reused as U = alpha*V1@A1^T + beta*V2@A2^T.
__device__ float g_dw[201326592];
__device__ float g_q[4194304];      // [input][b][m][hw]
__device__ float g_k[4194304];
__device__ float g_fused[33554432]; // [b][c][hw]
__device__ float g_psum[131072];    // [b][g][hwtile][2] (8*32*128*2 used)
__device__ float2 g_stats[256];     // [b][g]

// ---- K1: fused depthwise 3x3 (q,k,v) on both inputs ----
__global__ __launch_bounds__(256) void dw_kernel(
    const float* __restrict__ img, const float* __restrict__ mask,
    const float* __restrict__ qw, const float* __restrict__ qb,
    const float* __restrict__ kw, const float* __restrict__ kb,
    const float* __restrict__ vw, const float* __restrict__ vb)
{
    int bid = blockIdx.x;
    int band = bid & 15;
    int bc = (bid >> 4) & 2047;
    int input = bid >> 15;
    int c = bc & 255;
    const float* src = (input ? mask : img) + (size_t)bc * HWSZ;

    __shared__ float s[10 * 132];
    int t = threadIdx.x;
    int y0 = band * 8;
    for (int i = t; i < 10 * 130; i += 256) {
        int r = i / 130, cc = i - r * 130;
        int gy = y0 - 1 + r, gx = cc - 1;
        float v = 0.f;
        if ((unsigned)gy < 128u && (unsigned)gx < 128u) v = src[gy * 128 + gx];
        s[r * 132 + cc] = v;
    }
    float wq[9], wk[9], wv[9];
#pragma unroll
    for (int j = 0; j < 9; j++) { wq[j]=qw[c*9+j]; wk[j]=kw[c*9+j]; wv[j]=vw[c*9+j]; }
    float bq = qb[c], bk = kb[c], bv = vb[c];
    __syncthreads();

    int x = t & 127, quad = t >> 7;
    float aq[4], ak[4], av[4];
#pragma unroll
    for (int r = 0; r < 4; r++) { aq[r]=bq; ak[r]=bk; av[r]=bv; }
#pragma unroll
    for (int dx = 0; dx < 3; dx++) {
        float col[6];
#pragma unroll
        for (int rr = 0; rr < 6; rr++) col[rr] = s[(quad*4+rr)*132 + x + dx];
#pragma unroll
        for (int r = 0; r < 4; r++)
#pragma unroll
            for (int dy = 0; dy < 3; dy++) {
                float v = col[r + dy]; int j = dy*3 + dx;
                aq[r] += wq[j]*v; ak[r] += wk[j]*v; av[r] += wv[j]*v;
            }
    }
    float* dq = g_dw + ((size_t)(0 + input)*2048 + bc)*(size_t)HWSZ;
    float* dk = g_dw + ((size_t)(2 + input)*2048 + bc)*(size_t)HWSZ;
    float* dv = g_dw + ((size_t)(4 + input)*2048 + bc)*(size_t)HWSZ;
#pragma unroll
    for (int r = 0; r < 4; r++) {
        int y = y0 + quad*4 + r;
        dq[y*128 + x] = aq[r]; dk[y*128 + x] = ak[r]; dv[y*128 + x] = av[r];
    }
}

// ---- K2: q/k pointwise (16x256 per pixel) ----
__global__ __launch_bounds__(256) void pwqk_kernel(
    const float* __restrict__ qpw_w, const float* __restrict__ qpw_b,
    const float* __restrict__ kpw_w, const float* __restrict__ kpw_b)
{
    int which = blockIdx.y;
    int input = which & 1, proj = which >> 1;
    const float* Wp = proj ? kpw_w : qpw_w;
    const float* bp = proj ? kpw_b : qpw_b;
    const float* dwb = g_dw + (size_t)(proj*2 + input)*2048*(size_t)HWSZ;
    float* outb = (proj ? g_k : g_q) + (size_t)input*8*CMID*HWSZ;

    __shared__ float4 ws[CMID*64];
    __shared__ float  bs[CMID];
    int t = threadIdx.x;
    for (int i = t; i < CMID*64; i += 256) ws[i] = ((const float4*)Wp)[i];
    if (t < CMID) bs[t] = bp[t];
    __syncthreads();

    int n = blockIdx.x*256 + t;
    int b = n >> 14, hw = n & 16383;
    const float* xp = dwb + ((size_t)b*CCH)*HWSZ + hw;
    float acc[CMID];
#pragma unroll
    for (int m = 0; m < CMID; m++) acc[m] = bs[m];
#pragma unroll 4
    for (int c4 = 0; c4 < 64; c4++) {
        float x0 = xp[(size_t)(4*c4+0)*HWSZ];
        float x1 = xp[(size_t)(4*c4+1)*HWSZ];
        float x2 = xp[(size_t)(4*c4+2)*HWSZ];
        float x3 = xp[(size_t)(4*c4+3)*HWSZ];
#pragma unroll
        for (int m = 0; m < CMID; m++) {
            float4 w = ws[m*64 + c4];
            acc[m] += w.x*x0 + w.y*x1 + w.z*x2 + w.w*x3;
        }
    }
    float* op = outb + ((size_t)b*CMID)*HWSZ + hw;
#pragma unroll
    for (int m = 0; m < CMID; m++) op[(size_t)m*HWSZ] = acc[m];
}

// ---- K3 helpers ----
__device__ __forceinline__ void qk_gemm(const float* sQ, const float* sK, float* sSt, int t)
{
    int tx = t & 15, ty = t >> 4;
    int q0 = tx*4, p0 = ty*4;
    float a[4][4];
#pragma unroll
    for (int i=0;i<4;i++)
#pragma unroll
        for (int j=0;j<4;j++) a[i][j]=0.f;
#pragma unroll
    for (int c = 0; c < 16; c++) {
        float4 kk = *(const float4*)&sK[c*64 + q0];
        float4 qq = *(const float4*)&sQ[c*64 + p0];
        float kr[4]={kk.x,kk.y,kk.z,kk.w}, qr[4]={qq.x,qq.y,qq.z,qq.w};
#pragma unroll
        for (int i=0;i<4;i++)
#pragma unroll
            for (int j=0;j<4;j++) a[i][j] += kr[i]*qr[j];
    }
#pragma unroll
    for (int i=0;i<4;i++)
#pragma unroll
        for (int j=0;j<4;j++) sSt[(q0+i)*68 + p0+j] = 0.25f*a[i][j];
}

__device__ __forceinline__ void softmax_col(float* sSt, int p, float scale)
{
    float mx = -1e30f;
    for (int q = 0; q < 64; q++) mx = fmaxf(mx, sSt[q*68+p]);
    float sum = 0.f;
    for (int q = 0; q < 64; q++) { float e = __expf(sSt[q*68+p]-mx); sSt[q*68+p]=e; sum+=e; }
    float inv = scale / sum;
    for (int q = 0; q < 64; q++) sSt[q*68+p] *= inv;
}

__device__ __forceinline__ void t_accum(float acc[8][8], const float* sV, const float* sSt,
                                        int c0, int p0)
{
#pragma unroll 2
    for (int q = 0; q < 64; q++) {
        float av[8];
#pragma unroll
        for (int i=0;i<8;i++) av[i] = sV[(c0+i)*65 + q];
        float4 u0 = *(const float4*)&sSt[q*68 + p0];
        float4 u1 = *(const float4*)&sSt[q*68 + p0 + 4];
        float uu[8]={u0.x,u0.y,u0.z,u0.w,u1.x,u1.y,u1.z,u1.w};
#pragma unroll
        for (int i=0;i<8;i++)
#pragma unroll
            for (int j=0;j<8;j++) acc[i][j] += av[i]*uu[j];
    }
}

// smem (floats): Q 0..1024, K 1024..2048, St1 2048(4352), St2 6400(4352), V 10752(16640)
#define ATTN_SMEM_FLOATS 27392

// ---- K3: attention both directions, writes U = alpha*V1@A1^T + beta*V2@A2^T ----
__global__ __launch_bounds__(256, 1) void attn_kernel(
    const float* __restrict__ alpha_p, const float* __restrict__ beta_p)
{
    extern __shared__ float sm[];
    float* sQ   = sm;
    float* sK   = sm + 1024;
    float* sSt1 = sm + 2048;
    float* sSt2 = sm + 6400;
    float* sV   = sm + 10752;

    int t = threadIdx.x;
    int bid = blockIdx.x;
    int b = bid >> 8, blkid = bid & 255;
    int by = blkid >> 4, bx = blkid & 15;
    float al = __ldg(alpha_p), be = __ldg(beta_p);
    int hw00 = by*8*128 + bx*8;

    {   // dir1: Q=mask, K=img
        const float* qs = g_q + (((size_t)8 + b)*CMID)*HWSZ;
        const float* ks = g_k + (((size_t)0 + b)*CMID)*HWSZ;
        for (int e = t; e < 1024; e += 256) {
            int m = e >> 6, p = e & 63;
            int hw = hw00 + ((p>>3)<<7) + (p&7);
            sQ[m*64+p] = qs[(size_t)m*HWSZ + hw];
            sK[m*64+p] = ks[(size_t)m*HWSZ + hw];
        }
    }
    __syncthreads();
    qk_gemm(sQ, sK, sSt1, t);
    __syncthreads();
    {   // dir2 load + softmax(St1, alpha)
        const float* qs = g_q + (((size_t)0 + b)*CMID)*HWSZ;
        const float* ks = g_k + (((size_t)8 + b)*CMID)*HWSZ;
        for (int e = t; e < 1024; e += 256) {
            int m = e >> 6, p = e & 63;
            int hw = hw00 + ((p>>3)<<7) + (p&7);
            sQ[m*64+p] = qs[(size_t)m*HWSZ + hw];
            sK[m*64+p] = ks[(size_t)m*HWSZ + hw];
        }
        if (t < 64) softmax_col(sSt1, t, al);
    }
    __syncthreads();
    qk_gemm(sQ, sK, sSt2, t);
    __syncthreads();
    {   // load dwv(img) + softmax(St2, beta)
        const float* vs = g_dw + (((size_t)4*8 + b)*CCH)*(size_t)HWSZ;
        for (int e = t; e < 256*64; e += 256) {
            int c = e >> 6, q = e & 63;
            int hw = hw00 + ((q>>3)<<7) + (q&7);
            sV[c*65+q] = vs[(size_t)c*HWSZ + hw];
        }
        if (t < 64) softmax_col(sSt2, t, be);
    }
    __syncthreads();

    int pg = t & 7, cg = t >> 3;
    int c0 = cg*8, p0 = pg*8;
    float acc[8][8];
#pragma unroll
    for (int i=0;i<8;i++)
#pragma unroll
        for (int j=0;j<8;j++) acc[i][j]=0.f;

    t_accum(acc, sV, sSt1, c0, p0);
    __syncthreads();
    {
        const float* vs = g_dw + (((size_t)5*8 + b)*CCH)*(size_t)HWSZ;
        for (int e = t; e < 256*64; e += 256) {
            int c = e >> 6, q = e & 63;
            int hw = hw00 + ((q>>3)<<7) + (q&7);
            sV[c*65+q] = vs[(size_t)c*HWSZ + hw];
        }
    }
    __syncthreads();
    t_accum(acc, sV, sSt2, c0, p0);

    // write U to g_dw region 0 (layout [b][c][hw]); thread covers c0..c0+7,
    // pixels p0..p0+7 = spatial row pg of the block -> 8 contiguous hw
    size_t ub0 = (((size_t)b*CCH + c0) << 14) + (size_t)hw00 + ((size_t)pg << 7);
#pragma unroll
    for (int i = 0; i < 8; i++) {
        size_t ga = ub0 + ((size_t)i << 14);
        *(float4*)&g_dw[ga]   = make_float4(acc[i][0],acc[i][1],acc[i][2],acc[i][3]);
        *(float4*)&g_dw[ga+4] = make_float4(acc[i][4],acc[i][5],acc[i][6],acc[i][7]);
    }
}

// ---- K4: tf32 tensor-core GEMM: fused = Wv x U + ab*bv + img + mask, GN partials ----
__device__ __forceinline__ unsigned f2tf(float f)
{ unsigned r; asm("cvt.rna.tf32.f32 %0, %1;" : "=r"(r) : "f"(f)); return r; }

__device__ __forceinline__ void mma_tf32(float d[4], const unsigned a[4], const unsigned bb[2])
{
    asm volatile("mma.sync.aligned.m16n8k8.row.col.f32.tf32.tf32.f32 "
        "{%0,%1,%2,%3},{%4,%5,%6,%7},{%8,%9},{%0,%1,%2,%3};"
        : "+f"(d[0]),"+f"(d[1]),"+f"(d[2]),"+f"(d[3])
        : "r"(a[0]),"r"(a[1]),"r"(a[2]),"r"(a[3]),"r"(bb[0]),"r"(bb[1]));
}

// smem: sA[2][32*136] + sB[2][32*136] = 17408 u32 = 69632 B; epilogue stage 128x129 f32
#define GEMM_SMEM_BYTES 69632

__global__ __launch_bounds__(256, 1) void gemm_kernel(
    const float* __restrict__ Wv, const float* __restrict__ bvp,
    const float* __restrict__ img, const float* __restrict__ mask,
    const float* __restrict__ alpha_p, const float* __restrict__ beta_p)
{
    extern __shared__ unsigned sg[];
    unsigned* sAb[2] = { sg, sg + 4352 };
    unsigned* sBb[2] = { sg + 8704, sg + 13056 };

    const int t = threadIdx.x, lane = t & 31, warp = t >> 5;
    const int warpM = warp >> 2, warpN = warp & 3;
    const int hwt = blockIdx.x, mt = blockIdx.y, b = blockIdx.z;
    const int n0 = hwt * 128;
    const float* U = g_dw;

    float d[4][4][4];
#pragma unroll
    for (int i=0;i<4;i++)
#pragma unroll
        for (int j=0;j<4;j++)
#pragma unroll
            for (int e=0;e<4;e++) d[i][j][e]=0.f;

    // prologue: tile 0 -> buffer 0
    {
#pragma unroll
        for (int s = 0; s < 4; s++) {
            int fid = s*256 + t;
            { int row = fid >> 3, c4 = fid & 7;
              float4 v = *(const float4*)&Wv[(size_t)(mt*128+row)*256 + c4*4];
              int ba = (c4*4)*136 + row;
              sAb[0][ba]=f2tf(v.x); sAb[0][ba+136]=f2tf(v.y);
              sAb[0][ba+272]=f2tf(v.z); sAb[0][ba+408]=f2tf(v.w); }
            { int kr = fid >> 5, cc = (fid & 31)*4;
              float4 v = *(const float4*)&U[((size_t)(b*256+kr) << 14) + n0 + cc];
              int ba = kr*136 + cc;
              sBb[0][ba]=f2tf(v.x); sBb[0][ba+1]=f2tf(v.y);
              sBb[0][ba+2]=f2tf(v.z); sBb[0][ba+3]=f2tf(v.w); }
        }
    }
    __syncthreads();

    float4 ra[4], rb[4];
    for (int kt = 0; kt < 8; kt++) {
        int cur = kt & 1;
        if (kt < 7) {
            int kc = (kt+1)*32;
#pragma unroll
            for (int s = 0; s < 4; s++) {
                int fid = s*256 + t;
                int row = fid >> 3, c4 = fid & 7;
                ra[s] = *(const float4*)&Wv[(size_t)(mt*128+row)*256 + kc + c4*4];
                int kr = fid >> 5, cc = (fid & 31)*4;
                rb[s] = *(const float4*)&U[((size_t)(b*256+kc+kr) << 14) + n0 + cc];
            }
        }
        const unsigned* sA = sAb[cur];
        const unsigned* sB = sBb[cur];
#pragma unroll
        for (int ks = 0; ks < 4; ks++) {
            int kb = ks*8;
            int ar = kb + (lane & 3), am = lane >> 2;
            unsigned a[4][4], bb[4][2];
#pragma unroll
            for (int i = 0; i < 4; i++) {
                int mi = warpM*64 + i*16 + am;
                a[i][0] = sA[ar*136 + mi];      a[i][1] = sA[ar*136 + mi + 8];
                a[i][2] = sA[(ar+4)*136 + mi];  a[i][3] = sA[(ar+4)*136 + mi + 8];
            }
#pragma unroll
            for (int j = 0; j < 4; j++) {
                int nj = warpN*32 + j*8 + am;
                bb[j][0] = sB[ar*136 + nj];
                bb[j][1] = sB[(ar+4)*136 + nj];
            }
#pragma unroll
            for (int i = 0; i < 4; i++)
#pragma unroll
                for (int j = 0; j < 4; j++) mma_tf32(d[i][j], a[i], bb[j]);
        }
        if (kt < 7) {
            int nxt = cur ^ 1;
#pragma unroll
            for (int s = 0; s < 4; s++) {
                int fid = s*256 + t;
                int row = fid >> 3, c4 = fid & 7;
                int ba = (c4*4)*136 + row;
                sAb[nxt][ba]=f2tf(ra[s].x); sAb[nxt][ba+136]=f2tf(ra[s].y);
                sAb[nxt][ba+272]=f2tf(ra[s].z); sAb[nxt][ba+408]=f2tf(ra[s].w);
                int kr = fid >> 5, cc = (fid & 31)*4;
                int bbase = kr*136 + cc;
                sBb[nxt][bbase]=f2tf(rb[s].x); sBb[nxt][bbase+1]=f2tf(rb[s].y);
                sBb[nxt][bbase+2]=f2tf(rb[s].z); sBb[nxt][bbase+3]=f2tf(rb[s].w);
            }
            __syncthreads();
        }
    }
    __syncthreads();   // done with sA/sB; reuse as epilogue staging

    float* stage = (float*)sg;   // 128 x 129
    float ab = __ldg(alpha_p) + __ldg(beta_p);
    int r = lane >> 2, cc = (lane & 3)*2;
#pragma unroll
    for (int i = 0; i < 4; i++) {
#pragma unroll
        for (int half = 0; half < 2; half++) {
            int ro = warpM*64 + i*16 + r + half*8;
            int o = mt*128 + ro;
            float bias = ab * __ldg(&bvp[o]);
#pragma unroll
            for (int j = 0; j < 4; j++) {
                int nl = warpN*32 + j*8 + cc;
                size_t g = ((size_t)(b*256 + o) << 14) + n0 + nl;
                float2 iv = *(const float2*)&img[g];
                float2 mv = *(const float2*)&mask[g];
                float v0 = d[i][j][half*2+0] + bias + iv.x + mv.x;
                float v1 = d[i][j][half*2+1] + bias + iv.y + mv.y;
                *(float2*)&g_fused[g] = make_float2(v0, v1);
                stage[ro*129 + nl]     = v0;
                stage[ro*129 + nl + 1] = v1;
            }
        }
    }
    __syncthreads();

    // GN partials: sum / sumsq per 8-channel group over this 128-px tile
    int row = t >> 1, hf = t & 1;
    float s = 0.f, q = 0.f;
#pragma unroll 8
    for (int x = 0; x < 64; x++) {
        float v = stage[row*129 + hf*64 + x];
        s += v; q += v*v;
    }
    s += __shfl_xor_sync(0xffffffffu, s, 1);
    q += __shfl_xor_sync(0xffffffffu, q, 1);
    __shared__ float rs[128], rq[128];
    if (!hf) { rs[row] = s; rq[row] = q; }
    __syncthreads();
    if (t < 16) {
        float ss = 0.f, qq = 0.f;
#pragma unroll
        for (int k = 0; k < 8; k++) { ss += rs[t*8+k]; qq += rq[t*8+k]; }
        int g = mt*16 + t;
        int idx = ((b*32 + g)*128 + hwt)*2;
        g_psum[idx] = ss; g_psum[idx+1] = qq;
    }
}

// ---- K5: reduce GN partials (128 per group) ----
__global__ __launch_bounds__(128) void stats_kernel()
{
    int bg = blockIdx.x, t = threadIdx.x;
    float2 v = ((const float2*)g_psum)[bg*128 + t];
    float s = v.x, q = v.y;
#pragma unroll
    for (int o = 16; o; o >>= 1) {
        s += __shfl_xor_sync(0xffffffffu, s, o);
        q += __shfl_xor_sync(0xffffffffu, q, o);
    }
    __shared__ float ss[4], qs[4];
    if ((t & 31) == 0) { ss[t>>5] = s; qs[t>>5] = q; }
    __syncthreads();
    if (t == 0) {
        for (int w = 1; w < 4; w++) { s += ss[w]; q += qs[w]; }
        float inv = 1.f / 131072.f;
        float mu = s * inv;
        float var = q * inv - mu*mu;
        g_stats[bg] = make_float2(mu, rsqrtf(var + 1e-5f));
    }
}

// ---- K6: normalize ----
__global__ __launch_bounds__(1024) void norm_kernel(
    float* __restrict__ out, const float* __restrict__ gamma, const float* __restrict__ beta)
{
    int i4 = blockIdx.x*1024 + threadIdx.x;
    size_t e = (size_t)i4 << 2;
    int b = (int)(e >> 22), c = (int)(e >> 14) & 255;
    float2 st = g_stats[b*32 + (c >> 3)];
    float gsc = gamma[c] * st.y;
    float bsh = beta[c] - st.x * gsc;
    float4 f = *(const float4*)&g_fused[e];
    float4 r;
    r.x = f.x*gsc + bsh; r.y = f.y*gsc + bsh;
    r.z = f.z*gsc + bsh; r.w = f.w*gsc + bsh;
    *(float4*)&out[e] = r;
}

extern "C" void kernel_launch(void* const* d_in, const int* in_sizes, int n_in,
                              void* d_out, int out_size)
{
    const float* img    = (const float*)d_in[0];
    const float* mask   = (const float*)d_in[1];
    const float* qdw_w  = (const float*)d_in[2];
    const float* qdw_b  = (const float*)d_in[3];
    const float* kdw_w  = (const float*)d_in[4];
    const float* kdw_b  = (const float*)d_in[5];
    const float* vdw_w  = (const float*)d_in[6];
    const float* vdw_b  = (const float*)d_in[7];
    const float* qpw_w  = (const float*)d_in[8];
    const float* qpw_b  = (const float*)d_in[9];
    const float* kpw_w  = (const float*)d_in[10];
    const float* kpw_b  = (const float*)d_in[11];
    const float* vpw_w  = (const float*)d_in[12];
    const float* vpw_b  = (const float*)d_in[13];
    const float* alpha  = (const float*)d_in[14];
    const float* beta   = (const float*)d_in[15];
    const float* gn_w   = (const float*)d_in[16];
    const float* gn_b   = (const float*)d_in[17];

    cudaFuncSetAttribute(attn_kernel, cudaFuncAttributeMaxDynamicSharedMemorySize,
                         ATTN_SMEM_FLOATS * 4);
    cudaFuncSetAttribute(gemm_kernel, cudaFuncAttributeMaxDynamicSharedMemorySize,
                         GEMM_SMEM_BYTES);

    dw_kernel<<<65536, 256>>>(img, mask, qdw_w, qdw_b, kdw_w, kdw_b, vdw_w, vdw_b);
    dim3 g2(512, 4);
    pwqk_kernel<<<g2, 256>>>(qpw_w, qpw_b, kpw_w, kpw_b);
    attn_kernel<<<2048, 256, ATTN_SMEM_FLOATS * 4>>>(alpha, beta);
    dim3 g4(128, 2, 8);
    gemm_kernel<<<g4, 256, GEMM_SMEM_BYTES>>>(vpw_w, vpw_b, img, mask, alpha, beta);
    stats_kernel<<<256, 128>>>();
    norm_kernel<<<8192, 1024>>>((float*)d_out, gn_w, gn_b);
}